// round 6
// baseline (speedup 1.0000x reference)
#include <cuda_runtime.h>
#include <cstdint>

// ConstituencyMFVI: B=8, N=192, 3 mean-field iterations.
// q[b,i,j] = s_span[b,i,j] + (j>i) * sum_{k != i, k != j} sigmoid(q[b,i,k]) * s_pair[b,i,j,k]
// out = sigmoid(q).
//
// Cluster(3) per (b,i) tile; CTA rank c owns 64 rows j in (i+64c, i+64c+64],
// one row per thread (64 threads), row fully resident in SMEM (50.5KB/CTA ->
// 4 CTAs/SM). Rows j<=i are never loaded (mask=0 analytically): 113MB HBM.
// Per iteration, each thread multicasts sigma(q_j) to all 3 cluster CTAs'
// sig buffer (mapa + st.shared::cluster); double-buffered sig => exactly one
// barrier.cluster per iteration.
//
// R5 bugfix: exclusion zeroing must happen AFTER the cluster barrier. A row's
// chunks are loaded by many threads, and cp.async.wait_group only drains the
// calling thread's groups; pre-barrier zero writes raced with other threads'
// in-flight cp.asyncs. Post-barrier (everyone drained own groups before
// arriving) all loads are complete, and the zeroing thread == reading thread.

namespace {
constexpr int NN   = 192;
constexpr int RPC  = 64;    // rows per CTA
constexpr int PAD  = 196;   // row stride in floats (196 % 8 == 4 -> conflict-free LDS.128)
constexpr int THREADS = 64;
constexpr int CPR  = 48;    // 16B chunks per row
}

__device__ __forceinline__ float sigmoidf(float x) {
    return 1.0f / (1.0f + __expf(-x));
}

__device__ __forceinline__ void cluster_sync_() {
    asm volatile("barrier.cluster.arrive.aligned;\n" ::: "memory");
    asm volatile("barrier.cluster.wait.aligned;\n" ::: "memory");
}

// store v to the sig word at shared-address `laddr` inside cluster CTA `rank`
__device__ __forceinline__ void st_cluster(uint32_t laddr, int rank, float v) {
    asm volatile("{\n\t"
                 ".reg .u32 ra;\n\t"
                 "mapa.shared::cluster.u32 ra, %0, %1;\n\t"
                 "st.shared::cluster.f32 [ra], %2;\n\t"
                 "}\n"
                 :: "r"(laddr), "r"(rank), "f"(v) : "memory");
}

__global__ __launch_bounds__(THREADS, 4) __cluster_dims__(3, 1, 1)
void mfvi_kernel(const float* __restrict__ s_span,
                 const float* __restrict__ s_pair,
                 float* __restrict__ out)
{
    extern __shared__ float sm[];
    float* tile = sm;                    // [RPC][PAD]
    float* sig0 = sm + RPC * PAD;        // [NN]
    float* sig1 = sig0 + NN;             // [NN]

    const int c = blockIdx.x;            // cluster rank (0..2)
    const int i = blockIdx.y;
    const int b = blockIdx.z;
    const int t = threadIdx.x;

    const int R      = NN - 1 - i;                        // active rows (j > i)
    const int nvalid = min(RPC, max(0, R - c * RPC));     // rows this CTA owns
    const bool valid = t < nvalid;
    const int j      = i + 1 + c * RPC + t;               // my row

    const size_t base = (size_t)(b * NN + i);
    const float* gs = s_span + base * NN;
    const float* gP = s_pair + base * (size_t)(NN * NN);  // [j][k]

    const uint32_t stile = (uint32_t)__cvta_generic_to_shared(tile);

    // ---- issue loads for this CTA's rows (coalesced 16B chunks) ----
    const int totch = nvalid * CPR;
    for (int g = t; g < totch; g += THREADS) {
        int slot = g / CPR;
        int col  = g - slot * CPR;
        int row  = i + 1 + c * RPC + slot;
        uint32_t dst = stile + (uint32_t)(slot * PAD + col * 4) * 4u;
        const float* src = gP + (size_t)row * NN + col * 4;
        asm volatile("cp.async.cg.shared.global [%0], [%1], 16;\n" :: "r"(dst), "l"(src));
    }
    asm volatile("cp.async.commit_group;\n");

    // ---- constant sigma for k <= i into BOTH buffers; rank 0 writes those outputs ----
    for (int j2 = t; j2 <= i; j2 += THREADS) {
        float v = sigmoidf(gs[j2]);
        sig0[j2] = v;
        sig1[j2] = v;
        if (c == 0) out[base * NN + j2] = v;
    }

    const uint32_t ssig0 = (uint32_t)__cvta_generic_to_shared(sig0);
    const uint32_t ssig1 = ssig0 + NN * 4u;

    float s = 0.0f;
    if (valid) {
        s = gs[j];
        float v = sigmoidf(s);                 // sigma^0 of my row
        #pragma unroll
        for (int rk = 0; rk < 3; rk++) st_cluster(ssig0 + (uint32_t)j * 4u, rk, v);
    }

    // drain my own cp.async groups, then barrier: post-barrier, every thread's
    // groups are drained -> the whole tile is resident in all cluster CTAs.
    asm volatile("cp.async.wait_group 0;\n");
    cluster_sync_();                           // sig0 complete + all tiles loaded

    if (valid) {                               // zero excluded k entries (my own row;
        tile[t * PAD + i] = 0.0f;              //  same thread reads it below)
        tile[t * PAD + j] = 0.0f;
    }

    const float4* row4 = reinterpret_cast<const float4*>(tile + t * PAD);
    float q = s;

    #pragma unroll 1
    for (int it = 0; it < 3; it++) {
        const float4* sg4 = reinterpret_cast<const float4*>((it & 1) ? sig1 : sig0);
        if (valid) {
            float ax = 0.f, ay = 0.f, az = 0.f, aw = 0.f;
            #pragma unroll
            for (int cc = 0; cc < CPR; cc++) {
                float4 p  = row4[cc];
                float4 sg = sg4[cc];
                ax = fmaf(p.x, sg.x, ax);
                ay = fmaf(p.y, sg.y, ay);
                az = fmaf(p.z, sg.z, az);
                aw = fmaf(p.w, sg.w, aw);
            }
            q = s + ((ax + ay) + (az + aw));
        }
        if (it < 2) {
            if (valid) {
                float v = sigmoidf(q);
                uint32_t dstbuf = (it & 1) ? ssig0 : ssig1;   // write the buffer NOT being read
                #pragma unroll
                for (int rk = 0; rk < 3; rk++) st_cluster(dstbuf + (uint32_t)j * 4u, rk, v);
            }
            cluster_sync_();
        }
    }

    if (valid) out[base * NN + j] = sigmoidf(q);
}

extern "C" void kernel_launch(void* const* d_in, const int* in_sizes, int n_in,
                              void* d_out, int out_size)
{
    const float* s_span = (const float*)d_in[0];
    const float* s_pair = (const float*)d_in[1];
    float* out = (float*)d_out;

    size_t smem = (size_t)(RPC * PAD + 2 * NN) * sizeof(float);  // 51,712 B -> 4 CTAs/SM
    cudaFuncSetAttribute(mfvi_kernel,
                         cudaFuncAttributeMaxDynamicSharedMemorySize, (int)smem);

    dim3 grid(3, NN, 8);   // x = cluster rank, y = i (big tiles first), z = b
    mfvi_kernel<<<grid, THREADS, smem>>>(s_span, s_pair, out);
}

// round 7
// speedup vs baseline: 1.3313x; 1.3313x over previous
#include <cuda_runtime.h>
#include <cuda.h>
#include <cstdint>

// ConstituencyMFVI: B=8, N=192, 3 mean-field iterations.
// q[b,i,j] = s_span[b,i,j] + (j>i) * sum_{k != i, k != j} sigmoid(q[b,i,k]) * s_pair[b,i,j,k]
// out = sigmoid(q).
//
// R7: loads via TMA (cp.async.bulk.tensor.3d) instead of cp.async -- the
// per-warp outstanding-load cap (~55) limited cp.async to ~3 TB/s chip-wide;
// the TMA engine is not subject to it. Tensor = [k=192, j=192, tile=1536],
// box = [96, 48, 1]; row overshoot past j=191 is OOB-zero-filled.
// Shape as R3: one CTA per (b,i), 192 threads, thread t owns row j=i+1+t.
// Low k-half [0,96) cached in regs (24 x float4), high half stays in SMEM.
// Unpadded 384B rows (TMA layout); bank conflicts avoided by per-thread
// rotation: thread t accesses chunk (t+cc) % 24 (distinct mod 8 within each
// 8-lane LDS.128 phase => conflict-free).

namespace {
constexpr int NN      = 192;
constexpr int HALF    = 96;
constexpr int CH      = 24;     // float4 chunks per half row
constexpr int BOXROWS = 48;
constexpr int BOXBYTES = BOXROWS * HALF * 4;     // 18432
constexpr int THREADS = 192;
constexpr int TILE_BYTES = NN * HALF * 4;        // 73728
constexpr int SIG_OFF    = TILE_BYTES;           // floats region
constexpr int MBAR_OFF   = TILE_BYTES + NN * 4;  // two 8B mbarriers
}

__device__ __forceinline__ float sigmoidf(float x) {
    return 1.0f / (1.0f + __expf(-x));
}

__device__ __forceinline__ void mbar_init(uint32_t a, uint32_t cnt) {
    asm volatile("mbarrier.init.shared.b64 [%0], %1;\n" :: "r"(a), "r"(cnt) : "memory");
}
__device__ __forceinline__ void mbar_expect_tx(uint32_t a, uint32_t bytes) {
    asm volatile("mbarrier.arrive.expect_tx.shared.b64 _, [%0], %1;\n" :: "r"(a), "r"(bytes) : "memory");
}
__device__ __forceinline__ void mbar_wait0(uint32_t a) {
    asm volatile("{\n\t"
                 ".reg .pred P;\n\t"
                 "WL_%=:\n\t"
                 "mbarrier.try_wait.parity.acquire.cta.shared::cta.b64 P, [%0], 0, 0x989680;\n\t"
                 "@P bra.uni WD_%=;\n\t"
                 "bra.uni WL_%=;\n\t"
                 "WD_%=:\n\t"
                 "}\n" :: "r"(a) : "memory");
}
__device__ __forceinline__ void tma_load3d(uint32_t dst, const CUtensorMap* m,
                                           int x, int y, int z, uint32_t mbar) {
    asm volatile("cp.async.bulk.tensor.3d.shared::cta.global.tile.mbarrier::complete_tx::bytes "
                 "[%0], [%1, {%2, %3, %4}], [%5];\n"
                 :: "r"(dst), "l"(m), "r"(x), "r"(y), "r"(z), "r"(mbar) : "memory");
}

__global__ __launch_bounds__(THREADS, 2)
void mfvi_kernel(const __grid_constant__ CUtensorMap tmap,
                 const float* __restrict__ s_span,
                 float* __restrict__ out)
{
    extern __shared__ float sm[];
    float* buf = sm;                         // [192 rows][96 floats], unpadded
    float* sig = sm + TILE_BYTES / 4;        // [192]

    const int i = blockIdx.x;
    const int b = blockIdx.y;
    const int t = threadIdx.x;

    const int R     = NN - 1 - i;            // active rows (j > i)
    const bool valid = t < R;
    const int j     = i + 1 + t;             // my row (if valid)
    const int nb    = (R + BOXROWS - 1) / BOXROWS;   // boxes per half (0..4)
    const int tilez = b * NN + i;

    const size_t base = (size_t)tilez;
    const float* gs = s_span + base * NN;

    const uint32_t sbuf  = (uint32_t)__cvta_generic_to_shared(buf);
    const uint32_t smbar = (uint32_t)__cvta_generic_to_shared(sm) + MBAR_OFF;

    if (t == 0) {
        mbar_init(smbar, 1);
        mbar_init(smbar + 8, 1);
    }
    __syncthreads();

    // ---- phase 1: TMA low half (cols 0..95) ----
    if (t == 0) {
        mbar_expect_tx(smbar, (uint32_t)(nb * BOXBYTES));
        for (int bi = 0; bi < nb; bi++)
            tma_load3d(sbuf + bi * BOXROWS * HALF * 4, &tmap,
                       0, i + 1 + bi * BOXROWS, tilez, smbar);
    }

    // overlap scalar setup with inbound data
    if (t <= i) {                            // constant outputs for j2 = t <= i
        float v = sigmoidf(gs[t]);
        sig[t] = v;
        out[base * NN + t] = v;
    }
    float s = 0.0f;
    if (valid) {
        s = gs[j];
        sig[j] = sigmoidf(s);                // sigma^0 of my row
    }

    mbar_wait0(smbar);                       // low half resident (acquire)

    // zero excluded low-half entries, then cache my row to regs (rotated)
    const int rot = t % CH;
    float4 r[CH];
    if (valid) {
        float* myrow = buf + t * HALF;
        if (i < HALF) myrow[i] = 0.0f;       // k == i
        if (j < HALF) myrow[j] = 0.0f;       // k == j
        const float4* row4 = reinterpret_cast<const float4*>(myrow);
        #pragma unroll
        for (int cc = 0; cc < CH; cc++) {
            int idx = rot + cc; if (idx >= CH) idx -= CH;
            r[cc] = row4[idx];               // r[cc] holds col-chunk idx
        }
    }
    __syncthreads();                         // reg copies + sig publishes done

    // ---- phase 2: TMA high half (cols 96..191) into the same buffer ----
    if (t == 0) {
        asm volatile("fence.proxy.async.shared::cta;\n" ::: "memory");
        mbar_expect_tx(smbar + 8, (uint32_t)(nb * BOXBYTES));
        for (int bi = 0; bi < nb; bi++)
            tma_load3d(sbuf + bi * BOXROWS * HALF * 4, &tmap,
                       HALF, i + 1 + bi * BOXROWS, tilez, smbar + 8);
    }
    mbar_wait0(smbar + 8);

    if (valid) {                             // zero excluded high-half entries
        float* myrow = buf + t * HALF;
        if (i >= HALF) myrow[i - HALF] = 0.0f;
        if (j >= HALF) myrow[j - HALF] = 0.0f;
    }

    const float4* row4 = reinterpret_cast<const float4*>(buf + t * HALF);
    const float4* sig4 = reinterpret_cast<const float4*>(sig);
    float q = s;

    #pragma unroll 1
    for (int it = 0; it < 3; it++) {
        if (valid) {
            float ax = 0.f, ay = 0.f, az = 0.f, aw = 0.f;
            #pragma unroll
            for (int cc = 0; cc < CH; cc++) {        // low half: regs
                int idx = rot + cc; if (idx >= CH) idx -= CH;
                float4 sg = sig4[idx];
                ax = fmaf(r[cc].x, sg.x, ax);
                ay = fmaf(r[cc].y, sg.y, ay);
                az = fmaf(r[cc].z, sg.z, az);
                aw = fmaf(r[cc].w, sg.w, aw);
            }
            #pragma unroll
            for (int cc = 0; cc < CH; cc++) {        // high half: SMEM (rotated)
                int idx = rot + cc; if (idx >= CH) idx -= CH;
                float4 p  = row4[idx];
                float4 sg = sig4[CH + idx];
                ax = fmaf(p.x, sg.x, ax);
                ay = fmaf(p.y, sg.y, ay);
                az = fmaf(p.z, sg.z, az);
                aw = fmaf(p.w, sg.w, aw);
            }
            q = s + ((ax + ay) + (az + aw));
        }
        if (it < 2) {
            __syncthreads();                 // all reads of sig done
            if (valid) sig[j] = sigmoidf(q);
            __syncthreads();
        }
    }

    if (valid) out[base * NN + j] = sigmoidf(q);
}

// --------------------------------------------------------------------------

typedef CUresult (*PFN_tmapEncode)(
    CUtensorMap*, CUtensorMapDataType, cuuint32_t, void*,
    const cuuint64_t*, const cuuint64_t*, const cuuint32_t*, const cuuint32_t*,
    CUtensorMapInterleave, CUtensorMapSwizzle, CUtensorMapL2promotion,
    CUtensorMapFloatOOBfill);

extern "C" void kernel_launch(void* const* d_in, const int* in_sizes, int n_in,
                              void* d_out, int out_size)
{
    const float* s_span = (const float*)d_in[0];
    void*        s_pair = (void*)d_in[1];
    float* out = (float*)d_out;

    // tensor map: [k=192, j=192, tile=1536], fp32, box [96,48,1], no swizzle
    PFN_tmapEncode pfn = nullptr;
    cudaDriverEntryPointQueryResult qres;
    cudaGetDriverEntryPoint("cuTensorMapEncodeTiled", (void**)&pfn,
                            cudaEnableDefault, &qres);

    CUtensorMap tmap;
    cuuint64_t dims[3]    = {NN, NN, (cuuint64_t)(NN * 8)};
    cuuint64_t strides[2] = {(cuuint64_t)NN * 4, (cuuint64_t)NN * NN * 4};
    cuuint32_t box[3]     = {HALF, BOXROWS, 1};
    cuuint32_t estr[3]    = {1, 1, 1};
    pfn(&tmap, CU_TENSOR_MAP_DATA_TYPE_FLOAT32, 3, s_pair,
        dims, strides, box, estr,
        CU_TENSOR_MAP_INTERLEAVE_NONE, CU_TENSOR_MAP_SWIZZLE_NONE,
        CU_TENSOR_MAP_L2_PROMOTION_L2_128B, CU_TENSOR_MAP_FLOAT_OOB_FILL_NONE);

    size_t smem = MBAR_OFF + 16;   // tile + sig + 2 mbarriers (~74.5 KB -> 2 CTAs/SM)
    cudaFuncSetAttribute(mfvi_kernel,
                         cudaFuncAttributeMaxDynamicSharedMemorySize, (int)smem);

    dim3 grid(NN, 8);              // x = i (big tiles first), y = b
    mfvi_kernel<<<grid, THREADS, smem>>>(tmap, s_span, out);
}